// round 1
// baseline (speedup 1.0000x reference)
#include <cuda_runtime.h>
#include <math.h>

// ---------------- problem constants ----------------
#define BB   16
#define TT   4096
#define NR   (BB*TT)       // 65536 rows
#define TSD  64
#define DE   128
#define HH   256
#define LDF  512
#define LDH  256           // LD/2
#define OD   10
#define NBLKS 6
#define EPSV 1e-5f
#define NCH  16            // scan chunks
#define CLEN 256           // chunk length; NCH*CLEN == TT

// ---------------- scratch (static device, allocation-free) ----------------
static __device__ float  g_yenc[(size_t)NR*DE];        // encoder output (residual target)
static __device__ float  g_h   [(size_t)NR*DE];        // running hidden
static __device__ float2 g_bu  [(size_t)NR*HH];        // Bu, overwritten in-place by scan state
static __device__ float  g_lru [(size_t)NR*DE];        // LRU block output
static __device__ float  g_glu [(size_t)NR*LDH];       // GLU output
static __device__ float  g_WB  [(size_t)NBLKS*DE*2*HH];// packed gamma-scaled B (re/im interleaved cols)
static __device__ float  g_WC  [(size_t)NBLKS*2*HH*DE];// packed [Cre; -Cim] rows interleaved
static __device__ float2 g_lam [NBLKS*HH];
static __device__ float  g_gamma[NBLKS*HH];
static __device__ float  g_bnpart[512*2*DE];
static __device__ float  g_bna[DE];
static __device__ float  g_bnb[DE];
static __device__ float2 g_carry[BB*NCH*HH];
static __device__ float2 g_inc  [BB*NCH*HH];

// ---------------- prep ----------------
__global__ void prep_lam_kernel(const float* __restrict__ nu_log,
                                const float* __restrict__ theta_log) {
    int blk = blockIdx.x;
    int h   = threadIdx.x;
    float nu = nu_log[blk*HH + h];
    float th = theta_log[blk*HH + h];
    float r  = expf(-expf(nu));
    float ang = expf(th);
    float sn, cs;
    sincosf(ang, &sn, &cs);
    float2 lam; lam.x = r*cs; lam.y = r*sn;
    g_lam[blk*HH + h]   = lam;
    g_gamma[blk*HH + h] = sqrtf(fmaxf(1.f - r*r, 1e-8f));
}

__global__ void prep_W_kernel(const float* __restrict__ Bre, const float* __restrict__ Bim,
                              const float* __restrict__ Cre, const float* __restrict__ Cim) {
    int id = blockIdx.x*blockDim.x + threadIdx.x;
    if (id >= NBLKS*HH*DE) return;
    int d   = id % DE;
    int h   = (id / DE) % HH;
    int blk = id / (DE*HH);
    float gma = g_gamma[blk*HH + h];
    // B: [NBLK,H,DE]; WB[blk][d][2h]=Bre*g, [2h+1]=Bim*g  (GEMM out cols interleave re/im)
    float br = Bre[((size_t)blk*HH + h)*DE + d];
    float bi = Bim[((size_t)blk*HH + h)*DE + d];
    g_WB[((size_t)blk*DE + d)*(2*HH) + 2*h]     = br*gma;
    g_WB[((size_t)blk*DE + d)*(2*HH) + 2*h + 1] = bi*gma;
    // C: [NBLK,DE,H]; WC rows interleave: row 2h = Cre[d][h] (as W[k][d]), row 2h+1 = -Cim
    float cr = Cre[((size_t)blk*DE + d)*HH + h];
    float ci = Cim[((size_t)blk*DE + d)*HH + h];
    g_WC[((size_t)blk*(2*HH) + 2*h)*DE + d]     = cr;
    g_WC[((size_t)blk*(2*HH) + 2*h + 1)*DE + d] = -ci;
}

// ---------------- batchnorm stats (deterministic two-stage) ----------------
__global__ void bn_stats1_kernel(const float* __restrict__ h) {
    int f = threadIdx.x;      // 128
    int g = blockIdx.x;       // 512 blocks * 128 rows
    const float* p = h + (size_t)g*128*DE + f;
    float s = 0.f, s2 = 0.f;
    #pragma unroll 4
    for (int r = 0; r < 128; r++) {
        float v = p[(size_t)r*DE];
        s += v;
        s2 = fmaf(v, v, s2);
    }
    g_bnpart[g*(2*DE) + f]      = s;
    g_bnpart[g*(2*DE) + DE + f] = s2;
}

__global__ void bn_stats2_kernel(const float* __restrict__ scale,
                                 const float* __restrict__ bias) {
    int f = threadIdx.x;
    float s = 0.f, s2 = 0.f;
    for (int i = 0; i < 512; i++) {
        s  += g_bnpart[i*(2*DE) + f];
        s2 += g_bnpart[i*(2*DE) + DE + f];
    }
    float mean = s * (1.f/NR);
    float var  = s2 * (1.f/NR) - mean*mean;
    float a = scale[f] * rsqrtf(var + EPSV);
    g_bna[f] = a;
    g_bnb[f] = fmaf(-mean, a, bias[f]);
}

// ---------------- generic fp32 GEMM, 64x64 tile, 4x4 per thread ----------------
// MODE_A: 0 plain A load, 1 apply BN affine (a[k]*x+b[k]) on A's K (feature) dim.
// EPI:    0 = (+bias if non-null)
//         1 = cproj: acc + (bna[col]*aux1[m,col]+bnb[col])*dvec[col]
//         2 = +bias[col] + aux1[m,col]   (residual)
template<int KDIM, int NCOLS, int MODE_A, int EPI>
__global__ void __launch_bounds__(256) gemm_kernel(
    const float* __restrict__ A, const float* __restrict__ W,
    float* __restrict__ C, const float* __restrict__ bias,
    const float* __restrict__ aux1, const float* __restrict__ dvec)
{
    __shared__ float As[16][68];
    __shared__ float Bs[16][68];
    const int tid = threadIdx.x;
    const int tx = tid & 15;
    const int ty = tid >> 4;
    const int bm = blockIdx.y << 6;
    const int bn = blockIdx.x << 6;
    const int arow = tid >> 2;        // 0..63
    const int ak   = (tid & 3) << 2;  // 0,4,8,12
    const int wk   = tid >> 4;        // 0..15
    const int wc   = (tid & 15) << 2; // 0..60

    float acc[4][4];
    #pragma unroll
    for (int i = 0; i < 4; i++)
        #pragma unroll
        for (int j = 0; j < 4; j++) acc[i][j] = 0.f;

    for (int k0 = 0; k0 < KDIM; k0 += 16) {
        float4 av = *(const float4*)(A + (size_t)(bm + arow)*KDIM + (k0 + ak));
        if (MODE_A == 1) {
            float4 aa = *(const float4*)(g_bna + k0 + ak);
            float4 ab = *(const float4*)(g_bnb + k0 + ak);
            av.x = fmaf(aa.x, av.x, ab.x);
            av.y = fmaf(aa.y, av.y, ab.y);
            av.z = fmaf(aa.z, av.z, ab.z);
            av.w = fmaf(aa.w, av.w, ab.w);
        }
        As[ak+0][arow] = av.x;
        As[ak+1][arow] = av.y;
        As[ak+2][arow] = av.z;
        As[ak+3][arow] = av.w;
        *(float4*)(&Bs[wk][wc]) = *(const float4*)(W + (size_t)(k0 + wk)*NCOLS + (bn + wc));
        __syncthreads();
        #pragma unroll
        for (int kk = 0; kk < 16; kk++) {
            float4 a4 = *(const float4*)(&As[kk][ty << 2]);
            float4 b4 = *(const float4*)(&Bs[kk][tx << 2]);
            float ar[4] = {a4.x, a4.y, a4.z, a4.w};
            float br[4] = {b4.x, b4.y, b4.z, b4.w};
            #pragma unroll
            for (int i = 0; i < 4; i++)
                #pragma unroll
                for (int j = 0; j < 4; j++)
                    acc[i][j] = fmaf(ar[i], br[j], acc[i][j]);
        }
        __syncthreads();
    }

    const int ncol = bn + (tx << 2);
    #pragma unroll
    for (int i = 0; i < 4; i++) {
        int m = bm + (ty << 2) + i;
        float4 r = make_float4(acc[i][0], acc[i][1], acc[i][2], acc[i][3]);
        if (EPI == 0) {
            if (bias != nullptr) {
                float4 bv = *(const float4*)(bias + ncol);
                r.x += bv.x; r.y += bv.y; r.z += bv.z; r.w += bv.w;
            }
        } else if (EPI == 1) {
            float4 hv = *(const float4*)(aux1 + (size_t)m*DE + ncol);
            float4 aa = *(const float4*)(g_bna + ncol);
            float4 ab = *(const float4*)(g_bnb + ncol);
            float4 dv = *(const float4*)(dvec + ncol);
            r.x += (fmaf(aa.x, hv.x, ab.x))*dv.x;
            r.y += (fmaf(aa.y, hv.y, ab.y))*dv.y;
            r.z += (fmaf(aa.z, hv.z, ab.z))*dv.z;
            r.w += (fmaf(aa.w, hv.w, ab.w))*dv.w;
        } else if (EPI == 2) {
            float4 bv = *(const float4*)(bias + ncol);
            float4 yv = *(const float4*)(aux1 + (size_t)m*NCOLS + ncol);
            r.x += bv.x + yv.x; r.y += bv.y + yv.y;
            r.z += bv.z + yv.z; r.w += bv.w + yv.w;
        }
        *(float4*)(C + (size_t)m*NCOLS + ncol) = r;
    }
}

// ---------------- fused W1 + GLU: out[n,j] = (zW1+b1)[j] * sigmoid((zW1+b1)[j+256]) ----------------
__global__ void __launch_bounds__(256) glu_kernel(
    const float* __restrict__ A,      // [NR, DE]
    const float* __restrict__ W,      // [DE, LDF]
    const float* __restrict__ bias,   // [LDF]
    float* __restrict__ Cout)         // [NR, LDH]
{
    __shared__ float As[16][68];
    __shared__ float Bs0[16][68];
    __shared__ float Bs1[16][68];
    const int tid = threadIdx.x;
    const int tx = tid & 15;
    const int ty = tid >> 4;
    const int bm = blockIdx.y << 6;
    const int bn = blockIdx.x << 6;   // 0..192
    const int arow = tid >> 2;
    const int ak   = (tid & 3) << 2;
    const int wk   = tid >> 4;
    const int wc   = (tid & 15) << 2;

    float acc0[4][4], acc1[4][4];
    #pragma unroll
    for (int i = 0; i < 4; i++)
        #pragma unroll
        for (int j = 0; j < 4; j++) { acc0[i][j] = 0.f; acc1[i][j] = 0.f; }

    for (int k0 = 0; k0 < DE; k0 += 16) {
        float4 av = *(const float4*)(A + (size_t)(bm + arow)*DE + (k0 + ak));
        As[ak+0][arow] = av.x;
        As[ak+1][arow] = av.y;
        As[ak+2][arow] = av.z;
        As[ak+3][arow] = av.w;
        *(float4*)(&Bs0[wk][wc]) = *(const float4*)(W + (size_t)(k0 + wk)*LDF + (bn + wc));
        *(float4*)(&Bs1[wk][wc]) = *(const float4*)(W + (size_t)(k0 + wk)*LDF + (LDH + bn + wc));
        __syncthreads();
        #pragma unroll
        for (int kk = 0; kk < 16; kk++) {
            float4 a4 = *(const float4*)(&As[kk][ty << 2]);
            float4 b4 = *(const float4*)(&Bs0[kk][tx << 2]);
            float4 c4 = *(const float4*)(&Bs1[kk][tx << 2]);
            float ar[4] = {a4.x, a4.y, a4.z, a4.w};
            float br[4] = {b4.x, b4.y, b4.z, b4.w};
            float cr[4] = {c4.x, c4.y, c4.z, c4.w};
            #pragma unroll
            for (int i = 0; i < 4; i++)
                #pragma unroll
                for (int j = 0; j < 4; j++) {
                    acc0[i][j] = fmaf(ar[i], br[j], acc0[i][j]);
                    acc1[i][j] = fmaf(ar[i], cr[j], acc1[i][j]);
                }
        }
        __syncthreads();
    }

    const int ncol = bn + (tx << 2);
    float4 ba = *(const float4*)(bias + ncol);
    float4 bb = *(const float4*)(bias + LDH + ncol);
    #pragma unroll
    for (int i = 0; i < 4; i++) {
        int m = bm + (ty << 2) + i;
        float g0 = acc0[i][0] + ba.x, s0 = acc1[i][0] + bb.x;
        float g1 = acc0[i][1] + ba.y, s1 = acc1[i][1] + bb.y;
        float g2 = acc0[i][2] + ba.z, s2 = acc1[i][2] + bb.z;
        float g3 = acc0[i][3] + ba.w, s3 = acc1[i][3] + bb.w;
        float4 r;
        r.x = g0 * (1.f/(1.f + expf(-s0)));
        r.y = g1 * (1.f/(1.f + expf(-s1)));
        r.z = g2 * (1.f/(1.f + expf(-s2)));
        r.w = g3 * (1.f/(1.f + expf(-s3)));
        *(float4*)(Cout + (size_t)m*LDH + ncol) = r;
    }
}

// ---------------- LRU scan (chunked, 3 passes) ----------------
__device__ __forceinline__ float2 cstep(float2 lam, float2 s, float2 u) {
    float2 t;
    t.x = fmaf(lam.x, s.x, fmaf(-lam.y, s.y, u.x));
    t.y = fmaf(lam.x, s.y, fmaf( lam.y, s.x, u.y));
    return t;
}

__global__ void scanA_kernel(int blk) {
    int g  = blockIdx.x*256 + threadIdx.x;   // 65536 threads
    int h  = g & 255;
    int bc = g >> 8;                          // b*NCH + c
    int b  = bc >> 4;
    int c  = bc & 15;
    float2 lam = g_lam[blk*HH + h];
    float2 s = make_float2(0.f, 0.f);
    const float2* bu = g_bu + (size_t)(b*TT + c*CLEN)*HH + h;
    #pragma unroll 4
    for (int i = 0; i < CLEN; i++) {
        float2 u = bu[(size_t)i*HH];
        s = cstep(lam, s, u);
    }
    g_carry[bc*HH + h] = s;
}

__global__ void scanB_kernel(int blk) {
    int b = blockIdx.x;     // 16
    int h = threadIdx.x;    // 256
    float2 lam = g_lam[blk*HH + h];
    float2 lp = lam;        // lam^256 via 8 squarings
    #pragma unroll
    for (int i = 0; i < 8; i++) {
        float2 t;
        t.x = lp.x*lp.x - lp.y*lp.y;
        t.y = 2.f*lp.x*lp.y;
        lp = t;
    }
    float2 s = make_float2(0.f, 0.f);
    for (int c = 0; c < NCH; c++) {
        g_inc[(b*NCH + c)*HH + h] = s;
        float2 cr = g_carry[(b*NCH + c)*HH + h];
        s = cstep(lp, s, cr);
    }
}

__global__ void scanC_kernel(int blk) {
    int g  = blockIdx.x*256 + threadIdx.x;
    int h  = g & 255;
    int bc = g >> 8;
    int b  = bc >> 4;
    int c  = bc & 15;
    float2 lam = g_lam[blk*HH + h];
    float2 s = g_inc[bc*HH + h];
    float2* bu = g_bu + (size_t)(b*TT + c*CLEN)*HH + h;
    #pragma unroll 4
    for (int i = 0; i < CLEN; i++) {
        float2 u = bu[(size_t)i*HH];
        s = cstep(lam, s, u);
        bu[(size_t)i*HH] = s;   // in-place: state replaces Bu
    }
}

// ---------------- final: mean-pool over T + output head ----------------
__global__ void final_kernel(const float* __restrict__ h,
                             const float* __restrict__ Wout,
                             const float* __restrict__ bout,
                             float* __restrict__ out) {
    __shared__ float pooled[DE];
    int b = blockIdx.x;     // 16
    int f = threadIdx.x;    // 128
    float s = 0.f;
    const float* p = h + (size_t)b*TT*DE + f;
    #pragma unroll 4
    for (int t = 0; t < TT; t++) s += p[(size_t)t*DE];
    pooled[f] = s * (1.f/TT);
    __syncthreads();
    if (f < OD) {
        float acc = bout[f];
        #pragma unroll 4
        for (int d = 0; d < DE; d++) acc = fmaf(pooled[d], Wout[d*OD + f], acc);
        out[b*OD + f] = acc;
    }
}

// ---------------- launch ----------------
extern "C" void kernel_launch(void* const* d_in, const int* in_sizes, int n_in,
                              void* d_out, int out_size) {
    const float* x         = (const float*)d_in[0];
    const float* nu_log    = (const float*)d_in[1];
    const float* theta_log = (const float*)d_in[2];
    const float* B_re      = (const float*)d_in[3];
    const float* B_im      = (const float*)d_in[4];
    const float* C_re      = (const float*)d_in[5];
    const float* C_im      = (const float*)d_in[6];
    const float* D_lru     = (const float*)d_in[7];
    const float* W1        = (const float*)d_in[8];
    const float* b1        = (const float*)d_in[9];
    const float* W2        = (const float*)d_in[10];
    const float* b2        = (const float*)d_in[11];
    const float* bn_scale  = (const float*)d_in[12];
    const float* bn_bias   = (const float*)d_in[13];
    const float* W_enc     = (const float*)d_in[14];
    const float* b_enc     = (const float*)d_in[15];
    const float* W_out     = (const float*)d_in[16];
    const float* b_out     = (const float*)d_in[17];
    float* out = (float*)d_out;

    float *yenc, *h, *lru, *glu, *wb, *wc;
    float2* bu;
    cudaGetSymbolAddress((void**)&yenc, g_yenc);
    cudaGetSymbolAddress((void**)&h,    g_h);
    cudaGetSymbolAddress((void**)&bu,   g_bu);
    cudaGetSymbolAddress((void**)&lru,  g_lru);
    cudaGetSymbolAddress((void**)&glu,  g_glu);
    cudaGetSymbolAddress((void**)&wb,   g_WB);
    cudaGetSymbolAddress((void**)&wc,   g_WC);

    prep_lam_kernel<<<NBLKS, HH>>>(nu_log, theta_log);
    prep_W_kernel<<<(NBLKS*HH*DE + 255)/256, 256>>>(B_re, B_im, C_re, C_im);

    // encoder: y_enc = x @ W_enc + b_enc
    gemm_kernel<TSD, DE, 0, 0><<<dim3(DE/64, NR/64), 256>>>(
        x, W_enc, yenc, b_enc, nullptr, nullptr);

    const float* hp = yenc;
    for (int blk = 0; blk < NBLKS; blk++) {
        bn_stats1_kernel<<<512, 128>>>(hp);
        bn_stats2_kernel<<<1, 128>>>(bn_scale + blk*DE, bn_bias + blk*DE);

        // Bu = BN(h) @ WB  (re/im interleaved cols -> float2 [B,T,H])
        gemm_kernel<DE, 2*HH, 1, 0><<<dim3(2*HH/64, NR/64), 256>>>(
            hp, wb + (size_t)blk*DE*2*HH, (float*)bu, nullptr, nullptr, nullptr);

        scanA_kernel<<<NR/256, 256>>>(blk);
        scanB_kernel<<<BB, HH>>>(blk);
        scanC_kernel<<<NR/256, 256>>>(blk);

        // lru = Re(state @ C) + BN(h) * D
        gemm_kernel<2*HH, DE, 0, 1><<<dim3(DE/64, NR/64), 256>>>(
            (const float*)bu, wc + (size_t)blk*2*HH*DE, lru, nullptr, hp, D_lru + blk*DE);

        // glu = GLU(lru @ W1 + b1)
        glu_kernel<<<dim3(LDH/64, NR/64), 256>>>(
            lru, W1 + (size_t)blk*DE*LDF, b1 + (size_t)blk*LDF, glu);

        // h = glu @ W2 + b2 + y_enc
        gemm_kernel<LDH, DE, 0, 2><<<dim3(DE/64, NR/64), 256>>>(
            glu, W2 + (size_t)blk*LDH*DE, h, b2 + blk*DE, yenc, nullptr);

        hp = h;
    }

    final_kernel<<<BB, DE>>>(hp, W_out, b_out, out);
}

// round 3
// speedup vs baseline: 1.9180x; 1.9180x over previous
#include <cuda_runtime.h>
#include <cuda_bf16.h>
#include <math.h>
#include <stdint.h>

// ---------------- problem constants ----------------
#define BB   16
#define TT   4096
#define NR   (BB*TT)       // 65536 rows
#define TSD  64
#define DE   128
#define HH   256
#define LDF  512
#define LDH  256           // LD/2
#define OD   10
#define NBLKS 6
#define EPSV 1e-5f
#define NCH  16
#define CLEN 256

// ---------------- scratch (static device, allocation-free) ----------------
static __device__ __align__(256) float  g_yenc[(size_t)NR*DE];
static __device__ __align__(256) float  g_h   [(size_t)NR*DE];
static __device__ __align__(256) float2 g_bu  [(size_t)NR*HH];   // Bu / scan state in place
static __device__ __align__(256) float  g_lru [(size_t)NR*DE];
static __device__ __align__(256) float  g_glu [(size_t)NR*LDH];
static __device__ float2 g_lam [NBLKS*HH];
static __device__ float  g_gamma[NBLKS*HH];
static __device__ float  g_bnpart[512*2*DE];
static __device__ float  g_bna[DE];
static __device__ float  g_bnb[DE];
static __device__ float2 g_carry[BB*NCH*HH];
static __device__ float2 g_inc  [BB*NCH*HH];

// split bf16 weights, layout [blk][n][k]  (N-major rows, K contiguous)
static __device__ __align__(256) __nv_bfloat16 g_WBh[(size_t)NBLKS*512*128];
static __device__ __align__(256) __nv_bfloat16 g_WBl[(size_t)NBLKS*512*128];
static __device__ __align__(256) __nv_bfloat16 g_WCh[(size_t)NBLKS*128*512];
static __device__ __align__(256) __nv_bfloat16 g_WCl[(size_t)NBLKS*128*512];
static __device__ __align__(256) __nv_bfloat16 g_W1h[(size_t)NBLKS*512*128];
static __device__ __align__(256) __nv_bfloat16 g_W1l[(size_t)NBLKS*512*128];
static __device__ __align__(256) __nv_bfloat16 g_W2h[(size_t)NBLKS*128*256];
static __device__ __align__(256) __nv_bfloat16 g_W2l[(size_t)NBLKS*128*256];
static __device__ __align__(256) __nv_bfloat16 g_WEh[128*64];
static __device__ __align__(256) __nv_bfloat16 g_WEl[128*64];

// ---------------- prep ----------------
__global__ void prep_lam_kernel(const float* __restrict__ nu_log,
                                const float* __restrict__ theta_log) {
    int blk = blockIdx.x;
    int h   = threadIdx.x;
    float nu = nu_log[blk*HH + h];
    float th = theta_log[blk*HH + h];
    float r  = expf(-expf(nu));
    float ang = expf(th);
    float sn, cs;
    sincosf(ang, &sn, &cs);
    float2 lam; lam.x = r*cs; lam.y = r*sn;
    g_lam[blk*HH + h]   = lam;
    g_gamma[blk*HH + h] = sqrtf(fmaxf(1.f - r*r, 1e-8f));
}

__device__ __forceinline__ void split_store(float v, __nv_bfloat16* hi, __nv_bfloat16* lo, size_t i) {
    __nv_bfloat16 h = __float2bfloat16(v);
    hi[i] = h;
    lo[i] = __float2bfloat16(v - __bfloat162float(h));
}

__global__ void prep_WB_kernel(const float* __restrict__ Bre, const float* __restrict__ Bim) {
    int idx = blockIdx.x*256 + threadIdx.x;
    if (idx >= NBLKS*512*DE) return;
    int k = idx & 127;
    int n = (idx >> 7) & 511;
    int blk = idx >> 16;
    int h = n >> 1;
    float g = g_gamma[blk*HH + h];
    float v = ((n & 1) ? Bim : Bre)[((size_t)blk*HH + h)*DE + k] * g;
    split_store(v, g_WBh, g_WBl, idx);
}
__global__ void prep_WC_kernel(const float* __restrict__ Cre, const float* __restrict__ Cim) {
    int idx = blockIdx.x*256 + threadIdx.x;
    if (idx >= NBLKS*DE*512) return;
    int k = idx & 511;
    int n = (idx >> 9) & 127;
    int blk = idx >> 16;
    int h = k >> 1;
    float v = (k & 1) ? -Cim[((size_t)blk*DE + n)*HH + h] : Cre[((size_t)blk*DE + n)*HH + h];
    split_store(v, g_WCh, g_WCl, idx);
}
__global__ void prep_W1_kernel(const float* __restrict__ W1) {
    int idx = blockIdx.x*256 + threadIdx.x;
    if (idx >= NBLKS*512*DE) return;
    int k = idx & 127;
    int n = (idx >> 7) & 511;
    int blk = idx >> 16;
    float v = W1[((size_t)blk*DE + k)*LDF + n];
    split_store(v, g_W1h, g_W1l, idx);
}
__global__ void prep_W2_kernel(const float* __restrict__ W2) {
    int idx = blockIdx.x*256 + threadIdx.x;
    if (idx >= NBLKS*DE*256) return;
    int k = idx & 255;
    int n = (idx >> 8) & 127;
    int blk = idx >> 15;
    float v = W2[((size_t)blk*LDH + k)*DE + n];
    split_store(v, g_W2h, g_W2l, idx);
}
__global__ void prep_WE_kernel(const float* __restrict__ We) {
    int idx = blockIdx.x*256 + threadIdx.x;
    if (idx >= DE*TSD) return;
    int k = idx & 63;
    int n = idx >> 6;
    float v = We[(size_t)k*DE + n];
    split_store(v, g_WEh, g_WEl, idx);
}

// ---------------- batchnorm stats ----------------
__global__ void bn_stats1_kernel(const float* __restrict__ h) {
    int f = threadIdx.x;
    int g = blockIdx.x;
    const float* p = h + (size_t)g*128*DE + f;
    float s = 0.f, s2 = 0.f;
    #pragma unroll 4
    for (int r = 0; r < 128; r++) {
        float v = p[(size_t)r*DE];
        s += v;
        s2 = fmaf(v, v, s2);
    }
    g_bnpart[g*(2*DE) + f]      = s;
    g_bnpart[g*(2*DE) + DE + f] = s2;
}
__global__ void bn_stats2_kernel(const float* __restrict__ scale,
                                 const float* __restrict__ bias) {
    int f = threadIdx.x;
    float s = 0.f, s2 = 0.f;
    for (int i = 0; i < 512; i++) {
        s  += g_bnpart[i*(2*DE) + f];
        s2 += g_bnpart[i*(2*DE) + DE + f];
    }
    float mean = s * (1.f/NR);
    float var  = s2 * (1.f/NR) - mean*mean;
    float a = scale[f] * rsqrtf(var + EPSV);
    g_bna[f] = a;
    g_bnb[f] = fmaf(-mean, a, bias[f]);
}

// ---------------- bf16 mma.sync GEMM (HMMA path, works on compute_100) ----------------
#define MMA_BF16(d, a0, a1, a2, a3, b0, b1) \
    asm volatile("mma.sync.aligned.m16n8k16.row.col.f32.bf16.bf16.f32 " \
        "{%0,%1,%2,%3}, {%4,%5,%6,%7}, {%8,%9}, {%0,%1,%2,%3};" \
        : "+f"((d)[0]), "+f"((d)[1]), "+f"((d)[2]), "+f"((d)[3]) \
        : "r"(a0), "r"(a1), "r"(a2), "r"(a3), "r"(b0), "r"(b1))

// smem layout (bf16 units), pitch 72 per row (conflict-free fragment loads)
#define S_AH 0
#define S_AL (128*72)
#define S_BH (2*128*72)
#define S_BL (3*128*72)
#define SMEM_BF (4*128*72)           // 36864 bf16 = 73728 bytes

// D[128 x NT] tile per CTA. A fp32 (split on the fly), B pre-split bf16 [n][k].
// D = Ahi*Bhi + Alo*Bhi + Ahi*Blo.  MODE_A=1: BN affine on A.
// EPI: 0 = +bias(if set);  1 = + (bna*aux+bnb)*dvec;  2 = +bias + aux residual.
// DUAL=1: fused GLU: gate cols [bn,bn+64), sig cols [bn+256,+64); out = g*sigmoid(s).
template<int KDIM, int OUTW, int MODE_A, int EPI, int DUAL>
__global__ void __launch_bounds__(256, 2) gemm_mma(
    const float* __restrict__ A,
    const __nv_bfloat16* __restrict__ Bhi,
    const __nv_bfloat16* __restrict__ Blo,
    float* __restrict__ C,
    const float* __restrict__ bias,
    const float* __restrict__ aux,
    const float* __restrict__ dvec)
{
    extern __shared__ __nv_bfloat16 sm[];
    const int tid  = threadIdx.x;
    const int wid  = tid >> 5;
    const int lane = tid & 31;
    const int wr   = wid & 3;        // row-warp: rows 32*wr
    const int wc2  = wid >> 2;       // col-warp
    const int g    = lane >> 2;
    const int t    = lane & 3;
    const int bm   = blockIdx.y << 7;
    const int bn   = DUAL ? (blockIdx.x << 6) : (blockIdx.x << 7);

    float accg[2][DUAL ? 4 : 8][4];
    float accs[DUAL ? 2 : 1][DUAL ? 4 : 1][4];
    #pragma unroll
    for (int rb = 0; rb < 2; rb++)
        #pragma unroll
        for (int nb = 0; nb < (DUAL ? 4 : 8); nb++)
            #pragma unroll
            for (int j = 0; j < 4; j++) {
                accg[rb][nb][j] = 0.f;
                if (DUAL) accs[rb][nb][j] = 0.f;
            }

    for (int c = 0; c < KDIM/64; c++) {
        const int k0 = c*64;
        if (c) __syncthreads();
        // ---- stage A [128 x 64] fp32 -> split bf16 smem ----
        #pragma unroll
        for (int i = 0; i < 8; i++) {
            int idx  = tid + 256*i;
            int row  = idx >> 4;
            int col4 = (idx & 15) << 2;
            float4 v = *(const float4*)(A + (size_t)(bm + row)*KDIM + k0 + col4);
            if (MODE_A) {
                float4 aa = *(const float4*)(g_bna + k0 + col4);
                float4 ab = *(const float4*)(g_bnb + k0 + col4);
                v.x = fmaf(aa.x, v.x, ab.x);
                v.y = fmaf(aa.y, v.y, ab.y);
                v.z = fmaf(aa.z, v.z, ab.z);
                v.w = fmaf(aa.w, v.w, ab.w);
            }
            __nv_bfloat16 h0 = __float2bfloat16(v.x), h1 = __float2bfloat16(v.y);
            __nv_bfloat16 h2 = __float2bfloat16(v.z), h3 = __float2bfloat16(v.w);
            __nv_bfloat16 l0 = __float2bfloat16(v.x - __bfloat162float(h0));
            __nv_bfloat16 l1 = __float2bfloat16(v.y - __bfloat162float(h1));
            __nv_bfloat16 l2 = __float2bfloat16(v.z - __bfloat162float(h2));
            __nv_bfloat16 l3 = __float2bfloat16(v.w - __bfloat162float(h3));
            uint32_t hu0 = ((uint32_t)__bfloat16_as_ushort(h1) << 16) | __bfloat16_as_ushort(h0);
            uint32_t hu1 = ((uint32_t)__bfloat16_as_ushort(h3) << 16) | __bfloat16_as_ushort(h2);
            uint32_t lu0 = ((uint32_t)__bfloat16_as_ushort(l1) << 16) | __bfloat16_as_ushort(l0);
            uint32_t lu1 = ((uint32_t)__bfloat16_as_ushort(l3) << 16) | __bfloat16_as_ushort(l2);
            int off = row*72 + col4;
            *(uint2*)(sm + S_AH + off) = make_uint2(hu0, hu1);
            *(uint2*)(sm + S_AL + off) = make_uint2(lu0, lu1);
        }
        // ---- stage B [128 x 64] bf16 hi/lo ----
        #pragma unroll
        for (int i = 0; i < 8; i++) {
            int idx  = tid + 256*i;               // 2048 uint4 total
            int part = idx >> 10;                 // 0 hi, 1 lo
            int r    = (idx & 1023) >> 3;
            int q    = idx & 7;
            int rowg = DUAL ? (r < 64 ? bn + r : bn + 256 + (r - 64)) : (bn + r);
            const __nv_bfloat16* src = part ? Blo : Bhi;
            uint4 v = *(const uint4*)(src + (size_t)rowg*KDIM + k0 + q*8);
            *(uint4*)(sm + (part ? S_BL : S_BH) + r*72 + q*8) = v;
        }
        __syncthreads();

        // ---- compute 4 k16 steps ----
        #pragma unroll
        for (int kk = 0; kk < 4; kk++) {
            const int kb = kk*16 + 2*t;
            if (!DUAL) {
                uint32_t bh[8][2], bl[8][2];
                #pragma unroll
                for (int nb = 0; nb < 8; nb++) {
                    int boff = (64*wc2 + 8*nb + g)*72 + kb;
                    bh[nb][0] = *(const uint32_t*)(sm + S_BH + boff);
                    bh[nb][1] = *(const uint32_t*)(sm + S_BH + boff + 8);
                    bl[nb][0] = *(const uint32_t*)(sm + S_BL + boff);
                    bl[nb][1] = *(const uint32_t*)(sm + S_BL + boff + 8);
                }
                #pragma unroll
                for (int rb = 0; rb < 2; rb++) {
                    int aoff = (32*wr + 16*rb + g)*72 + kb;
                    uint32_t ah0 = *(const uint32_t*)(sm + S_AH + aoff);
                    uint32_t ah1 = *(const uint32_t*)(sm + S_AH + aoff + 8*72);
                    uint32_t ah2 = *(const uint32_t*)(sm + S_AH + aoff + 8);
                    uint32_t ah3 = *(const uint32_t*)(sm + S_AH + aoff + 8*72 + 8);
                    uint32_t al0 = *(const uint32_t*)(sm + S_AL + aoff);
                    uint32_t al1 = *(const uint32_t*)(sm + S_AL + aoff + 8*72);
                    uint32_t al2 = *(const uint32_t*)(sm + S_AL + aoff + 8);
                    uint32_t al3 = *(const uint32_t*)(sm + S_AL + aoff + 8*72 + 8);
                    #pragma unroll
                    for (int nb = 0; nb < 8; nb++) {
                        MMA_BF16(accg[rb][nb], ah0, ah1, ah2, ah3, bh[nb][0], bh[nb][1]);
                        MMA_BF16(accg[rb][nb], al0, al1, al2, al3, bh[nb][0], bh[nb][1]);
                        MMA_BF16(accg[rb][nb], ah0, ah1, ah2, ah3, bl[nb][0], bl[nb][1]);
                    }
                }
            } else {
                uint32_t bgh[4][2], bgl[4][2], bsh[4][2], bsl[4][2];
                #pragma unroll
                for (int nb = 0; nb < 4; nb++) {
                    int rg = 32*wc2 + 8*nb + g;
                    int bo = rg*72 + kb;
                    int so = (64 + rg)*72 + kb;
                    bgh[nb][0] = *(const uint32_t*)(sm + S_BH + bo);
                    bgh[nb][1] = *(const uint32_t*)(sm + S_BH + bo + 8);
                    bgl[nb][0] = *(const uint32_t*)(sm + S_BL + bo);
                    bgl[nb][1] = *(const uint32_t*)(sm + S_BL + bo + 8);
                    bsh[nb][0] = *(const uint32_t*)(sm + S_BH + so);
                    bsh[nb][1] = *(const uint32_t*)(sm + S_BH + so + 8);
                    bsl[nb][0] = *(const uint32_t*)(sm + S_BL + so);
                    bsl[nb][1] = *(const uint32_t*)(sm + S_BL + so + 8);
                }
                #pragma unroll
                for (int rb = 0; rb < 2; rb++) {
                    int aoff = (32*wr + 16*rb + g)*72 + kb;
                    uint32_t ah0 = *(const uint32_t*)(sm + S_AH + aoff);
                    uint32_t ah1 = *(const uint32_t*)(sm + S_AH + aoff + 8*72);
                    uint32_t ah2 = *(const uint32_t*)(sm + S_AH + aoff + 8);
                    uint32_t ah3 = *(const uint32_t*)(sm + S_AH + aoff + 8*72 + 8);
                    uint32_t al0 = *(const uint32_t*)(sm + S_AL + aoff);
                    uint32_t al1 = *(const uint32_t*)(sm + S_AL + aoff + 8*72);
                    uint32_t al2 = *(const uint32_t*)(sm + S_AL + aoff + 8);
                    uint32_t al3 = *(const uint32_t*)(sm + S_AL + aoff + 8*72 + 8);
                    #pragma unroll
                    for (int nb = 0; nb < 4; nb++) {
                        MMA_BF16(accg[rb][nb], ah0, ah1, ah2, ah3, bgh[nb][0], bgh[nb][1]);
                        MMA_BF16(accg[rb][nb], al0, al1, al2, al3, bgh[nb][0], bgh[nb][1]);
                        MMA_BF16(accg[rb][nb], ah0, ah1, ah2, ah3, bgl[nb][0], bgl[nb][1]);
                        MMA_BF16(accs[rb][nb], ah0, ah1, ah2, ah3, bsh[nb][0], bsh[nb][1]);
                        MMA_BF16(accs[rb][nb], al0, al1, al2, al3, bsh[nb][0], bsh[nb][1]);
                        MMA_BF16(accs[rb][nb], ah0, ah1, ah2, ah3, bsl[nb][0], bsl[nb][1]);
                    }
                }
            }
        }
    }

    // ---- epilogue ----
    #pragma unroll
    for (int rb = 0; rb < 2; rb++) {
        int m0 = bm + 32*wr + 16*rb + g;
        #pragma unroll
        for (int nb = 0; nb < (DUAL ? 4 : 8); nb++) {
            if (!DUAL) {
                int col = bn + 64*wc2 + 8*nb + 2*t;
                float2 v0 = make_float2(accg[rb][nb][0], accg[rb][nb][1]);   // row m0
                float2 v1 = make_float2(accg[rb][nb][2], accg[rb][nb][3]);   // row m0+8
                if (EPI == 0) {
                    if (bias != nullptr) {
                        float2 bv = *(const float2*)(bias + col);
                        v0.x += bv.x; v0.y += bv.y; v1.x += bv.x; v1.y += bv.y;
                    }
                } else if (EPI == 1) {
                    float2 aa = *(const float2*)(g_bna + col);
                    float2 ab = *(const float2*)(g_bnb + col);
                    float2 dv = *(const float2*)(dvec + col);
                    float2 h0 = *(const float2*)(aux + (size_t)m0*DE + col);
                    float2 h1 = *(const float2*)(aux + (size_t)(m0+8)*DE + col);
                    v0.x += fmaf(aa.x, h0.x, ab.x)*dv.x;
                    v0.y += fmaf(aa.y, h0.y, ab.y)*dv.y;
                    v1.x += fmaf(aa.x, h1.x, ab.x)*dv.x;
                    v1.y += fmaf(aa.y, h1.y, ab.y)*dv.y;
                } else if (EPI == 2) {
                    float2 bv = *(const float2*)(bias + col);
                    float2 y0 = *(const float2*)(aux + (size_t)m0*OUTW + col);
                    float2 y1 = *(const float2*)(aux + (size_t)(m0+8)*OUTW + col);
                    v0.x += bv.x + y0.x; v0.y += bv.y + y0.y;
                    v1.x += bv.x + y1.x; v1.y += bv.y + y1.y;
                }
                *(float2*)(C + (size_t)m0*OUTW + col)     = v0;
                *(float2*)(C + (size_t)(m0+8)*OUTW + col) = v1;
            } else {
                int jc = bn + 32*wc2 + 8*nb + 2*t;      // gate col, out col
                float2 bg = *(const float2*)(bias + jc);
                float2 bs = *(const float2*)(bias + 256 + jc);
                float g0 = accg[rb][nb][0] + bg.x, s0 = accs[rb][nb][0] + bs.x;
                float g1 = accg[rb][nb][1] + bg.y, s1 = accs[rb][nb][1] + bs.y;
                float g2 = accg[rb][nb][2] + bg.x, s2 = accs[rb][nb][2] + bs.x;
                float g3 = accg[rb][nb][3] + bg.y, s3 = accs[rb][nb][3] + bs.y;
                float2 v0, v1;
                v0.x = g0 * (1.f/(1.f + expf(-s0)));
                v0.y = g1 * (1.f/(1.f + expf(-s1)));
                v1.x = g2 * (1.f/(1.f + expf(-s2)));
                v1.y = g3 * (1.f/(1.f + expf(-s3)));
                *(float2*)(C + (size_t)m0*OUTW + jc)     = v0;
                *(float2*)(C + (size_t)(m0+8)*OUTW + jc) = v1;
            }
        }
    }
}

// ---------------- LRU scan (chunked, 3 passes) ----------------
__device__ __forceinline__ float2 cstep(float2 lam, float2 s, float2 u) {
    float2 t;
    t.x = fmaf(lam.x, s.x, fmaf(-lam.y, s.y, u.x));
    t.y = fmaf(lam.x, s.y, fmaf( lam.y, s.x, u.y));
    return t;
}
__global__ void scanA_kernel(int blk) {
    int g  = blockIdx.x*256 + threadIdx.x;
    int h  = g & 255;
    int bc = g >> 8;
    int b  = bc >> 4;
    int c  = bc & 15;
    float2 lam = g_lam[blk*HH + h];
    float2 s = make_float2(0.f, 0.f);
    const float2* bu = g_bu + (size_t)(b*TT + c*CLEN)*HH + h;
    #pragma unroll 4
    for (int i = 0; i < CLEN; i++) {
        float2 u = bu[(size_t)i*HH];
        s = cstep(lam, s, u);
    }
    g_carry[bc*HH + h] = s;
}
__global__ void scanB_kernel(int blk) {
    int b = blockIdx.x;
    int h = threadIdx.x;
    float2 lam = g_lam[blk*HH + h];
    float2 lp = lam;
    #pragma unroll
    for (int i = 0; i < 8; i++) {
        float2 t;
        t.x = lp.x*lp.x - lp.y*lp.y;
        t.y = 2.f*lp.x*lp.y;
        lp = t;
    }
    float2 s = make_float2(0.f, 0.f);
    for (int c = 0; c < NCH; c++) {
        g_inc[(b*NCH + c)*HH + h] = s;
        float2 cr = g_carry[(b*NCH + c)*HH + h];
        s = cstep(lp, s, cr);
    }
}
__global__ void scanC_kernel(int blk) {
    int g  = blockIdx.x*256 + threadIdx.x;
    int h  = g & 255;
    int bc = g >> 8;
    int b  = bc >> 4;
    int c  = bc & 15;
    float2 lam = g_lam[blk*HH + h];
    float2 s = g_inc[bc*HH + h];
    float2* bu = g_bu + (size_t)(b*TT + c*CLEN)*HH + h;
    #pragma unroll 4
    for (int i = 0; i < CLEN; i++) {
        float2 u = bu[(size_t)i*HH];
        s = cstep(lam, s, u);
        bu[(size_t)i*HH] = s;
    }
}

// ---------------- final: mean-pool + head ----------------
__global__ void final_kernel(const float* __restrict__ h,
                             const float* __restrict__ Wout,
                             const float* __restrict__ bout,
                             float* __restrict__ out) {
    __shared__ float pooled[DE];
    int b = blockIdx.x;
    int f = threadIdx.x;
    float s = 0.f;
    const float* p = h + (size_t)b*TT*DE + f;
    #pragma unroll 4
    for (int t = 0; t < TT; t++) s += p[(size_t)t*DE];
    pooled[f] = s * (1.f/TT);
    __syncthreads();
    if (f < OD) {
        float acc = bout[f];
        #pragma unroll 4
        for (int d = 0; d < DE; d++) acc = fmaf(pooled[d], Wout[d*OD + f], acc);
        out[b*OD + f] = acc;
    }
}

// ---------------- launch ----------------
#define SMEM_BYTES (SMEM_BF*2)   // 73728

extern "C" void kernel_launch(void* const* d_in, const int* in_sizes, int n_in,
                              void* d_out, int out_size) {
    const float* x         = (const float*)d_in[0];
    const float* nu_log    = (const float*)d_in[1];
    const float* theta_log = (const float*)d_in[2];
    const float* B_re      = (const float*)d_in[3];
    const float* B_im      = (const float*)d_in[4];
    const float* C_re      = (const float*)d_in[5];
    const float* C_im      = (const float*)d_in[6];
    const float* D_lru     = (const float*)d_in[7];
    const float* W1        = (const float*)d_in[8];
    const float* b1        = (const float*)d_in[9];
    const float* W2        = (const float*)d_in[10];
    const float* b2        = (const float*)d_in[11];
    const float* bn_scale  = (const float*)d_in[12];
    const float* bn_bias   = (const float*)d_in[13];
    const float* W_enc     = (const float*)d_in[14];
    const float* b_enc     = (const float*)d_in[15];
    const float* W_out     = (const float*)d_in[16];
    const float* b_out     = (const float*)d_in[17];
    float* out = (float*)d_out;

    float *yenc, *h, *lru, *glu;
    float2* bu;
    __nv_bfloat16 *wbh, *wbl, *wch, *wcl, *w1h, *w1l, *w2h, *w2l, *weh, *wel;
    cudaGetSymbolAddress((void**)&yenc, g_yenc);
    cudaGetSymbolAddress((void**)&h,    g_h);
    cudaGetSymbolAddress((void**)&bu,   g_bu);
    cudaGetSymbolAddress((void**)&lru,  g_lru);
    cudaGetSymbolAddress((void**)&glu,  g_glu);
    cudaGetSymbolAddress((void**)&wbh,  g_WBh);
    cudaGetSymbolAddress((void**)&wbl,  g_WBl);
    cudaGetSymbolAddress((void**)&wch,  g_WCh);
    cudaGetSymbolAddress((void**)&wcl,  g_WCl);
    cudaGetSymbolAddress((void**)&w1h,  g_W1h);
    cudaGetSymbolAddress((void**)&w1l,  g_W1l);
    cudaGetSymbolAddress((void**)&w2h,  g_W2h);
    cudaGetSymbolAddress((void**)&w2l,  g_W2l);
    cudaGetSymbolAddress((void**)&weh,  g_WEh);
    cudaGetSymbolAddress((void**)&wel,  g_WEl);

    cudaFuncSetAttribute(gemm_mma<64, 128, 0, 0, 0>,  cudaFuncAttributeMaxDynamicSharedMemorySize, SMEM_BYTES);
    cudaFuncSetAttribute(gemm_mma<128, 512, 1, 0, 0>, cudaFuncAttributeMaxDynamicSharedMemorySize, SMEM_BYTES);
    cudaFuncSetAttribute(gemm_mma<512, 128, 0, 1, 0>, cudaFuncAttributeMaxDynamicSharedMemorySize, SMEM_BYTES);
    cudaFuncSetAttribute(gemm_mma<128, 256, 0, 0, 1>, cudaFuncAttributeMaxDynamicSharedMemorySize, SMEM_BYTES);
    cudaFuncSetAttribute(gemm_mma<256, 128, 0, 2, 0>, cudaFuncAttributeMaxDynamicSharedMemorySize, SMEM_BYTES);

    prep_lam_kernel<<<NBLKS, HH>>>(nu_log, theta_log);
    prep_WB_kernel<<<(NBLKS*512*DE + 255)/256, 256>>>(B_re, B_im);
    prep_WC_kernel<<<(NBLKS*DE*512 + 255)/256, 256>>>(C_re, C_im);
    prep_W1_kernel<<<(NBLKS*512*DE + 255)/256, 256>>>(W1);
    prep_W2_kernel<<<(NBLKS*DE*256 + 255)/256, 256>>>(W2);
    prep_WE_kernel<<<(DE*TSD + 255)/256, 256>>>(W_enc);

    // encoder: y_enc = x @ W_enc + b_enc
    gemm_mma<64, 128, 0, 0, 0><<<dim3(1, NR/128), 256, SMEM_BYTES>>>(
        x, weh, wel, yenc, b_enc, nullptr, nullptr);

    const float* hp = yenc;
    for (int blk = 0; blk < NBLKS; blk++) {
        bn_stats1_kernel<<<512, 128>>>(hp);
        bn_stats2_kernel<<<1, 128>>>(bn_scale + blk*DE, bn_bias + blk*DE);

        // Bu = BN(h) @ WB
        gemm_mma<128, 512, 1, 0, 0><<<dim3(4, NR/128), 256, SMEM_BYTES>>>(
            hp, wbh + (size_t)blk*512*128, wbl + (size_t)blk*512*128,
            (float*)bu, nullptr, nullptr, nullptr);

        scanA_kernel<<<NR/256, 256>>>(blk);
        scanB_kernel<<<BB, HH>>>(blk);
        scanC_kernel<<<NR/256, 256>>>(blk);

        // lru = Re(state @ C) + BN(h) * D
        gemm_mma<512, 128, 0, 1, 0><<<dim3(1, NR/128), 256, SMEM_BYTES>>>(
            (const float*)bu, wch + (size_t)blk*128*512, wcl + (size_t)blk*128*512,
            lru, nullptr, hp, D_lru + blk*DE);

        // glu = GLU(lru @ W1 + b1)
        gemm_mma<128, 256, 0, 0, 1><<<dim3(4, NR/128), 256, SMEM_BYTES>>>(
            lru, w1h + (size_t)blk*512*128, w1l + (size_t)blk*512*128,
            glu, b1 + (size_t)blk*LDF, nullptr, nullptr);

        // h = glu @ W2 + b2 + y_enc
        gemm_mma<256, 128, 0, 2, 0><<<dim3(1, NR/128), 256, SMEM_BYTES>>>(
            glu, w2h + (size_t)blk*128*256, w2l + (size_t)blk*128*256,
            h, b2 + blk*DE, yenc, nullptr);

        hp = h;
    }

    final_kernel<<<BB, DE>>>(hp, W_out, b_out, out);
}

// round 4
// speedup vs baseline: 2.0309x; 1.0588x over previous
#include <cuda_runtime.h>
#include <cuda_bf16.h>
#include <math.h>
#include <stdint.h>

// ---------------- problem constants ----------------
#define BB   16
#define TT   4096
#define NR   (BB*TT)       // 65536 rows
#define TSD  64
#define DE   128
#define HH   256
#define LDF  512
#define LDH  256           // LD/2
#define OD   10
#define NBLKS 6
#define EPSV 1e-5f
#define NCH  16
#define CLEN 256

// ---------------- scratch (static device, allocation-free) ----------------
static __device__ __align__(256) float  g_yenc[(size_t)NR*DE];
static __device__ __align__(256) float  g_h   [(size_t)NR*DE];
static __device__ __align__(256) __nv_bfloat16 g_bu16[(size_t)NR*512];  // Bu / state, bf16, re/im interleaved
static __device__ __align__(256) float  g_lru [(size_t)NR*DE];
static __device__ __align__(256) float  g_glu [(size_t)NR*LDH];
static __device__ float2 g_lam [NBLKS*HH];
static __device__ float  g_gamma[NBLKS*HH];
static __device__ float  g_bnpart[512*2*DE];
static __device__ float  g_bna[DE];
static __device__ float  g_bnb[DE];
static __device__ float2 g_carry[BB*NCH*HH];
static __device__ float2 g_inc  [BB*NCH*HH];

// split bf16 weights, layout [blk][n][k]  (N-major rows, K contiguous)
static __device__ __align__(256) __nv_bfloat16 g_WBh[(size_t)NBLKS*512*128];
static __device__ __align__(256) __nv_bfloat16 g_WBl[(size_t)NBLKS*512*128];
static __device__ __align__(256) __nv_bfloat16 g_WCh[(size_t)NBLKS*128*512];
static __device__ __align__(256) __nv_bfloat16 g_WCl[(size_t)NBLKS*128*512];
static __device__ __align__(256) __nv_bfloat16 g_W1h[(size_t)NBLKS*512*128];
static __device__ __align__(256) __nv_bfloat16 g_W1l[(size_t)NBLKS*512*128];
static __device__ __align__(256) __nv_bfloat16 g_W2h[(size_t)NBLKS*128*256];
static __device__ __align__(256) __nv_bfloat16 g_W2l[(size_t)NBLKS*128*256];
static __device__ __align__(256) __nv_bfloat16 g_WEh[128*64];
static __device__ __align__(256) __nv_bfloat16 g_WEl[128*64];

// ---------------- helpers ----------------
__device__ __forceinline__ uint32_t smem_u32(const void* p) {
    uint32_t a;
    asm("{ .reg .u64 t; cvta.to.shared.u64 t, %1; cvt.u32.u64 %0, t; }" : "=r"(a) : "l"(p));
    return a;
}
__device__ __forceinline__ void cp16(uint32_t dst, const void* src) {
    asm volatile("cp.async.cg.shared.global [%0], [%1], 16;" :: "r"(dst), "l"(src));
}
#define CP_COMMIT() asm volatile("cp.async.commit_group;" ::: "memory")
#define CP_WAIT0()  asm volatile("cp.async.wait_group 0;" ::: "memory")

#define MMA_BF16(d, a0, a1, a2, a3, b0, b1) \
    asm volatile("mma.sync.aligned.m16n8k16.row.col.f32.bf16.bf16.f32 " \
        "{%0,%1,%2,%3}, {%4,%5,%6,%7}, {%8,%9}, {%0,%1,%2,%3};" \
        : "+f"((d)[0]), "+f"((d)[1]), "+f"((d)[2]), "+f"((d)[3]) \
        : "r"(a0), "r"(a1), "r"(a2), "r"(a3), "r"(b0), "r"(b1))

// ---------------- prep ----------------
__global__ void prep_lam_kernel(const float* __restrict__ nu_log,
                                const float* __restrict__ theta_log) {
    int blk = blockIdx.x;
    int h   = threadIdx.x;
    float nu = nu_log[blk*HH + h];
    float th = theta_log[blk*HH + h];
    float r  = expf(-expf(nu));
    float ang = expf(th);
    float sn, cs;
    sincosf(ang, &sn, &cs);
    float2 lam; lam.x = r*cs; lam.y = r*sn;
    g_lam[blk*HH + h]   = lam;
    g_gamma[blk*HH + h] = sqrtf(fmaxf(1.f - r*r, 1e-8f));
}

__device__ __forceinline__ void split_store(float v, __nv_bfloat16* hi, __nv_bfloat16* lo, size_t i) {
    __nv_bfloat16 h = __float2bfloat16(v);
    hi[i] = h;
    lo[i] = __float2bfloat16(v - __bfloat162float(h));
}

__global__ void prep_WB_kernel(const float* __restrict__ Bre, const float* __restrict__ Bim) {
    int idx = blockIdx.x*256 + threadIdx.x;
    if (idx >= NBLKS*512*DE) return;
    int k = idx & 127;
    int n = (idx >> 7) & 511;
    int blk = idx >> 16;
    int h = n >> 1;
    float g = g_gamma[blk*HH + h];
    float v = ((n & 1) ? Bim : Bre)[((size_t)blk*HH + h)*DE + k] * g;
    split_store(v, g_WBh, g_WBl, idx);
}
__global__ void prep_WC_kernel(const float* __restrict__ Cre, const float* __restrict__ Cim) {
    int idx = blockIdx.x*256 + threadIdx.x;
    if (idx >= NBLKS*DE*512) return;
    int k = idx & 511;
    int n = (idx >> 9) & 127;
    int blk = idx >> 16;
    int h = k >> 1;
    float v = (k & 1) ? -Cim[((size_t)blk*DE + n)*HH + h] : Cre[((size_t)blk*DE + n)*HH + h];
    split_store(v, g_WCh, g_WCl, idx);
}
__global__ void prep_W1_kernel(const float* __restrict__ W1) {
    int idx = blockIdx.x*256 + threadIdx.x;
    if (idx >= NBLKS*512*DE) return;
    int k = idx & 127;
    int n = (idx >> 7) & 511;
    int blk = idx >> 16;
    float v = W1[((size_t)blk*DE + k)*LDF + n];
    split_store(v, g_W1h, g_W1l, idx);
}
__global__ void prep_W2_kernel(const float* __restrict__ W2) {
    int idx = blockIdx.x*256 + threadIdx.x;
    if (idx >= NBLKS*DE*256) return;
    int k = idx & 255;
    int n = (idx >> 8) & 127;
    int blk = idx >> 15;
    float v = W2[((size_t)blk*LDH + k)*DE + n];
    split_store(v, g_W2h, g_W2l, idx);
}
__global__ void prep_WE_kernel(const float* __restrict__ We) {
    int idx = blockIdx.x*256 + threadIdx.x;
    if (idx >= DE*TSD) return;
    int k = idx & 63;
    int n = idx >> 6;
    float v = We[(size_t)k*DE + n];
    split_store(v, g_WEh, g_WEl, idx);
}

// ---------------- batchnorm stats ----------------
__global__ void bn_stats1_kernel(const float* __restrict__ h) {
    int f = threadIdx.x;
    int g = blockIdx.x;
    const float* p = h + (size_t)g*128*DE + f;
    float s = 0.f, s2 = 0.f;
    #pragma unroll 4
    for (int r = 0; r < 128; r++) {
        float v = p[(size_t)r*DE];
        s += v;
        s2 = fmaf(v, v, s2);
    }
    g_bnpart[g*(2*DE) + f]      = s;
    g_bnpart[g*(2*DE) + DE + f] = s2;
}
__global__ void bn_stats2_kernel(const float* __restrict__ scale,
                                 const float* __restrict__ bias) {
    int f = threadIdx.x;
    float s = 0.f, s2 = 0.f;
    for (int i = 0; i < 512; i++) {
        s  += g_bnpart[i*(2*DE) + f];
        s2 += g_bnpart[i*(2*DE) + DE + f];
    }
    float mean = s * (1.f/NR);
    float var  = s2 * (1.f/NR) - mean*mean;
    float a = scale[f] * rsqrtf(var + EPSV);
    g_bna[f] = a;
    g_bnb[f] = fmaf(-mean, a, bias[f]);
}

// ---------------- pipelined bf16 mma.sync GEMM ----------------
// smem pitch 72 bf16 per row. Stage buffers: [A_HI, (A_LO)], B_HI, B_LO. Double buffered.
// D = Ahi*Bhi (+ Alo*Bhi) + Ahi*Blo.
// MODE_A=1: BN affine on fp32 A. ABF16=1: A already bf16 (raw cp.async, 2 MMA terms).
// OUT16=1: store output as bf16. EPI: 0 +bias?; 1 cproj skip; 2 +bias+residual.
// DUAL=1: fused GLU (gate cols [bn,bn+64), sig cols [bn+256,+64)).
template<int KDIM, int OUTW, int MODE_A, int EPI, int DUAL, int ABF16, int OUT16>
__global__ void __launch_bounds__(256) gemm_mma(
    const void* __restrict__ Av,
    const __nv_bfloat16* __restrict__ Bhi,
    const __nv_bfloat16* __restrict__ Blo,
    float* __restrict__ C,
    const float* __restrict__ bias,
    const float* __restrict__ aux,
    const float* __restrict__ dvec)
{
    constexpr int UNIT   = 128*72;                 // elements per buffer
    constexpr int NBUFS  = ABF16 ? 3 : 4;
    constexpr int STRIDE = NBUFS*UNIT;             // per-stage elements
    constexpr int O_AH = 0;
    constexpr int O_AL = UNIT;                     // unused if ABF16
    constexpr int O_BH = ABF16 ? UNIT : 2*UNIT;
    constexpr int O_BL = O_BH + UNIT;
    constexpr int NCHK = KDIM / 64;

    extern __shared__ __nv_bfloat16 sm[];
    const uint32_t smb = smem_u32(sm);
    const int tid  = threadIdx.x;
    const int wid  = tid >> 5;
    const int lane = tid & 31;
    const int wr   = wid & 3;
    const int wc2  = wid >> 2;
    const int g    = lane >> 2;
    const int t    = lane & 3;
    const int bm   = blockIdx.y << 7;
    const int bn   = DUAL ? (blockIdx.x << 6) : (blockIdx.x << 7);

    float accg[2][DUAL ? 4 : 8][4];
    float accs[DUAL ? 2 : 1][DUAL ? 4 : 1][4];
    #pragma unroll
    for (int rb = 0; rb < 2; rb++)
        #pragma unroll
        for (int nb = 0; nb < (DUAL ? 4 : 8); nb++)
            #pragma unroll
            for (int j = 0; j < 4; j++) {
                accg[rb][nb][j] = 0.f;
                if (DUAL) accs[rb][nb][j] = 0.f;
            }

    float4 areg[8];
    auto loadA = [&](int cc) {
        const float* Af = (const float*)Av;
        #pragma unroll
        for (int i = 0; i < 8; i++) {
            int idx = tid + 256*i;
            int row = idx >> 4;
            int col4 = (idx & 15) << 2;
            areg[i] = *(const float4*)(Af + (size_t)(bm + row)*KDIM + cc*64 + col4);
        }
    };
    auto storeA = [&](int cc, int so) {
        #pragma unroll
        for (int i = 0; i < 8; i++) {
            int idx = tid + 256*i;
            int row = idx >> 4;
            int col4 = (idx & 15) << 2;
            float4 v = areg[i];
            if (MODE_A) {
                float4 aa = *(const float4*)(g_bna + cc*64 + col4);
                float4 ab = *(const float4*)(g_bnb + cc*64 + col4);
                v.x = fmaf(aa.x, v.x, ab.x);
                v.y = fmaf(aa.y, v.y, ab.y);
                v.z = fmaf(aa.z, v.z, ab.z);
                v.w = fmaf(aa.w, v.w, ab.w);
            }
            __nv_bfloat16 h0 = __float2bfloat16(v.x), h1 = __float2bfloat16(v.y);
            __nv_bfloat16 h2 = __float2bfloat16(v.z), h3 = __float2bfloat16(v.w);
            __nv_bfloat16 l0 = __float2bfloat16(v.x - __bfloat162float(h0));
            __nv_bfloat16 l1 = __float2bfloat16(v.y - __bfloat162float(h1));
            __nv_bfloat16 l2 = __float2bfloat16(v.z - __bfloat162float(h2));
            __nv_bfloat16 l3 = __float2bfloat16(v.w - __bfloat162float(h3));
            uint32_t hu0 = ((uint32_t)__bfloat16_as_ushort(h1) << 16) | __bfloat16_as_ushort(h0);
            uint32_t hu1 = ((uint32_t)__bfloat16_as_ushort(h3) << 16) | __bfloat16_as_ushort(h2);
            uint32_t lu0 = ((uint32_t)__bfloat16_as_ushort(l1) << 16) | __bfloat16_as_ushort(l0);
            uint32_t lu1 = ((uint32_t)__bfloat16_as_ushort(l3) << 16) | __bfloat16_as_ushort(l2);
            int off = row*72 + col4;
            *(uint2*)(sm + so + O_AH + off) = make_uint2(hu0, hu1);
            *(uint2*)(sm + so + O_AL + off) = make_uint2(lu0, lu1);
        }
    };
    auto cpA16 = [&](int cc, int so) {
        const __nv_bfloat16* Ab = (const __nv_bfloat16*)Av;
        #pragma unroll
        for (int i = 0; i < 4; i++) {
            int idx = tid + 256*i;
            int r = idx >> 3;
            int q = idx & 7;
            cp16(smb + (uint32_t)((so + O_AH + r*72 + q*8)*2),
                 Ab + (size_t)(bm + r)*KDIM + cc*64 + q*8);
        }
    };
    auto cpB = [&](int cc, int so) {
        #pragma unroll
        for (int i = 0; i < 8; i++) {
            int idx  = tid + 256*i;
            int part = idx >> 10;
            int r    = (idx & 1023) >> 3;
            int q    = idx & 7;
            int rowg = DUAL ? (r < 64 ? bn + r : bn + 256 + (r - 64)) : (bn + r);
            const __nv_bfloat16* src = part ? Blo : Bhi;
            cp16(smb + (uint32_t)((so + (part ? O_BL : O_BH) + r*72 + q*8)*2),
                 src + (size_t)rowg*KDIM + cc*64 + q*8);
        }
    };

    // prologue
    if (!ABF16) loadA(0); else cpA16(0, 0);
    cpB(0, 0);
    CP_COMMIT();
    if (!ABF16) {
        storeA(0, 0);
        if (NCHK > 1) loadA(1);
    }

    #pragma unroll 1
    for (int c = 0; c < NCHK; c++) {
        CP_WAIT0();
        __syncthreads();
        const int nso = ((c+1) & 1)*STRIDE;
        if (c + 1 < NCHK) {
            if (ABF16) cpA16(c+1, nso);
            cpB(c+1, nso);
            CP_COMMIT();
            if (!ABF16) {
                storeA(c+1, nso);
                if (c + 2 < NCHK) loadA(c+2);
            }
        }
        const int so = (c & 1)*STRIDE;

        #pragma unroll
        for (int kk = 0; kk < 4; kk++) {
            const int kb = kk*16 + 2*t;
            if (!DUAL) {
                uint32_t bh[8][2], bl[8][2];
                #pragma unroll
                for (int nb = 0; nb < 8; nb++) {
                    int boff = so + (64*wc2 + 8*nb + g)*72 + kb;
                    bh[nb][0] = *(const uint32_t*)(sm + O_BH + boff);
                    bh[nb][1] = *(const uint32_t*)(sm + O_BH + boff + 8);
                    bl[nb][0] = *(const uint32_t*)(sm + O_BL + boff);
                    bl[nb][1] = *(const uint32_t*)(sm + O_BL + boff + 8);
                }
                #pragma unroll
                for (int rb = 0; rb < 2; rb++) {
                    int aoff = so + (32*wr + 16*rb + g)*72 + kb;
                    uint32_t ah0 = *(const uint32_t*)(sm + O_AH + aoff);
                    uint32_t ah1 = *(const uint32_t*)(sm + O_AH + aoff + 8*72);
                    uint32_t ah2 = *(const uint32_t*)(sm + O_AH + aoff + 8);
                    uint32_t ah3 = *(const uint32_t*)(sm + O_AH + aoff + 8*72 + 8);
                    uint32_t al0 = 0, al1 = 0, al2 = 0, al3 = 0;
                    if (!ABF16) {
                        al0 = *(const uint32_t*)(sm + O_AL + aoff);
                        al1 = *(const uint32_t*)(sm + O_AL + aoff + 8*72);
                        al2 = *(const uint32_t*)(sm + O_AL + aoff + 8);
                        al3 = *(const uint32_t*)(sm + O_AL + aoff + 8*72 + 8);
                    }
                    #pragma unroll
                    for (int nb = 0; nb < 8; nb++) {
                        MMA_BF16(accg[rb][nb], ah0, ah1, ah2, ah3, bh[nb][0], bh[nb][1]);
                        if (!ABF16) MMA_BF16(accg[rb][nb], al0, al1, al2, al3, bh[nb][0], bh[nb][1]);
                        MMA_BF16(accg[rb][nb], ah0, ah1, ah2, ah3, bl[nb][0], bl[nb][1]);
                    }
                }
            } else {
                uint32_t bgh[4][2], bgl[4][2], bsh[4][2], bsl[4][2];
                #pragma unroll
                for (int nb = 0; nb < 4; nb++) {
                    int rg = 32*wc2 + 8*nb + g;
                    int bo = so + rg*72 + kb;
                    int so2 = so + (64 + rg)*72 + kb;
                    bgh[nb][0] = *(const uint32_t*)(sm + O_BH + bo);
                    bgh[nb][1] = *(const uint32_t*)(sm + O_BH + bo + 8);
                    bgl[nb][0] = *(const uint32_t*)(sm + O_BL + bo);
                    bgl[nb][1] = *(const uint32_t*)(sm + O_BL + bo + 8);
                    bsh[nb][0] = *(const uint32_t*)(sm + O_BH + so2);
                    bsh[nb][1] = *(const uint32_t*)(sm + O_BH + so2 + 8);
                    bsl[nb][0] = *(const uint32_t*)(sm + O_BL + so2);
                    bsl[nb][1] = *(const uint32_t*)(sm + O_BL + so2 + 8);
                }
                #pragma unroll
                for (int rb = 0; rb < 2; rb++) {
                    int aoff = so + (32*wr + 16*rb + g)*72 + kb;
                    uint32_t ah0 = *(const uint32_t*)(sm + O_AH + aoff);
                    uint32_t ah1 = *(const uint32_t*)(sm + O_AH + aoff + 8*72);
                    uint32_t ah2 = *(const uint32_t*)(sm + O_AH + aoff + 8);
                    uint32_t ah3 = *(const uint32_t*)(sm + O_AH + aoff + 8*72 + 8);
                    uint32_t al0 = *(const uint32_t*)(sm + O_AL + aoff);
                    uint32_t al1 = *(const uint32_t*)(sm + O_AL + aoff + 8*72);
                    uint32_t al2 = *(const uint32_t*)(sm + O_AL + aoff + 8);
                    uint32_t al3 = *(const uint32_t*)(sm + O_AL + aoff + 8*72 + 8);
                    #pragma unroll
                    for (int nb = 0; nb < 4; nb++) {
                        MMA_BF16(accg[rb][nb], ah0, ah1, ah2, ah3, bgh[nb][0], bgh[nb][1]);
                        MMA_BF16(accg[rb][nb], al0, al1, al2, al3, bgh[nb][0], bgh[nb][1]);
                        MMA_BF16(accg[rb][nb], ah0, ah1, ah2, ah3, bgl[nb][0], bgl[nb][1]);
                        MMA_BF16(accs[rb][nb], ah0, ah1, ah2, ah3, bsh[nb][0], bsh[nb][1]);
                        MMA_BF16(accs[rb][nb], al0, al1, al2, al3, bsh[nb][0], bsh[nb][1]);
                        MMA_BF16(accs[rb][nb], ah0, ah1, ah2, ah3, bsl[nb][0], bsl[nb][1]);
                    }
                }
            }
        }
    }

    // ---- epilogue ----
    #pragma unroll
    for (int rb = 0; rb < 2; rb++) {
        int m0 = bm + 32*wr + 16*rb + g;
        #pragma unroll
        for (int nb = 0; nb < (DUAL ? 4 : 8); nb++) {
            if (!DUAL) {
                int col = bn + 64*wc2 + 8*nb + 2*t;
                float2 v0 = make_float2(accg[rb][nb][0], accg[rb][nb][1]);
                float2 v1 = make_float2(accg[rb][nb][2], accg[rb][nb][3]);
                if (EPI == 0) {
                    if (bias != nullptr) {
                        float2 bv = *(const float2*)(bias + col);
                        v0.x += bv.x; v0.y += bv.y; v1.x += bv.x; v1.y += bv.y;
                    }
                } else if (EPI == 1) {
                    float2 aa = *(const float2*)(g_bna + col);
                    float2 ab = *(const float2*)(g_bnb + col);
                    float2 dv = *(const float2*)(dvec + col);
                    float2 h0 = *(const float2*)(aux + (size_t)m0*DE + col);
                    float2 h1 = *(const float2*)(aux + (size_t)(m0+8)*DE + col);
                    v0.x += fmaf(aa.x, h0.x, ab.x)*dv.x;
                    v0.y += fmaf(aa.y, h0.y, ab.y)*dv.y;
                    v1.x += fmaf(aa.x, h1.x, ab.x)*dv.x;
                    v1.y += fmaf(aa.y, h1.y, ab.y)*dv.y;
                } else if (EPI == 2) {
                    float2 bv = *(const float2*)(bias + col);
                    float2 y0 = *(const float2*)(aux + (size_t)m0*OUTW + col);
                    float2 y1 = *(const float2*)(aux + (size_t)(m0+8)*OUTW + col);
                    v0.x += bv.x + y0.x; v0.y += bv.y + y0.y;
                    v1.x += bv.x + y1.x; v1.y += bv.y + y1.y;
                }
                if (OUT16) {
                    __nv_bfloat16* C16 = (__nv_bfloat16*)C;
                    __nv_bfloat162 p0 = __floats2bfloat162_rn(v0.x, v0.y);
                    __nv_bfloat162 p1 = __floats2bfloat162_rn(v1.x, v1.y);
                    *(__nv_bfloat162*)(C16 + (size_t)m0*OUTW + col)     = p0;
                    *(__nv_bfloat162*)(C16 + (size_t)(m0+8)*OUTW + col) = p1;
                } else {
                    *(float2*)(C + (size_t)m0*OUTW + col)     = v0;
                    *(float2*)(C + (size_t)(m0+8)*OUTW + col) = v1;
                }
            } else {
                int jc = bn + 32*wc2 + 8*nb + 2*t;
                float2 bg = *(const float2*)(bias + jc);
                float2 bs = *(const float2*)(bias + 256 + jc);
                float g0 = accg[rb][nb][0] + bg.x, s0 = accs[rb][nb][0] + bs.x;
                float g1 = accg[rb][nb][1] + bg.y, s1 = accs[rb][nb][1] + bs.y;
                float g2 = accg[rb][nb][2] + bg.x, s2 = accs[rb][nb][2] + bs.x;
                float g3 = accg[rb][nb][3] + bg.y, s3 = accs[rb][nb][3] + bs.y;
                float2 v0, v1;
                v0.x = g0 * (1.f/(1.f + expf(-s0)));
                v0.y = g1 * (1.f/(1.f + expf(-s1)));
                v1.x = g2 * (1.f/(1.f + expf(-s2)));
                v1.y = g3 * (1.f/(1.f + expf(-s3)));
                *(float2*)(C + (size_t)m0*OUTW + jc)     = v0;
                *(float2*)(C + (size_t)(m0+8)*OUTW + jc) = v1;
            }
        }
    }
}

// ---------------- LRU scan (bf16 data, fp32 accumulation) ----------------
__device__ __forceinline__ float2 cstep(float2 lam, float2 s, float2 u) {
    float2 t;
    t.x = fmaf(lam.x, s.x, fmaf(-lam.y, s.y, u.x));
    t.y = fmaf(lam.x, s.y, fmaf( lam.y, s.x, u.y));
    return t;
}
__device__ __forceinline__ float2 bf2f(uint32_t raw) {
    __nv_bfloat162 u2 = *(__nv_bfloat162*)&raw;
    return make_float2(__bfloat162float(u2.x), __bfloat162float(u2.y));
}
__global__ void scanA_kernel(int blk) {
    int g  = blockIdx.x*256 + threadIdx.x;
    int h  = g & 255;
    int bc = g >> 8;
    int b  = bc >> 4;
    int c  = bc & 15;
    float2 lam = g_lam[blk*HH + h];
    float2 s = make_float2(0.f, 0.f);
    const uint32_t* bu = (const uint32_t*)g_bu16 + ((size_t)(b*TT + c*CLEN)*256 + h);
    #pragma unroll 8
    for (int i = 0; i < CLEN; i++) {
        float2 u = bf2f(bu[(size_t)i*256]);
        s = cstep(lam, s, u);
    }
    g_carry[bc*HH + h] = s;
}
__global__ void scanB_kernel(int blk) {
    int b = blockIdx.x;
    int h = threadIdx.x;
    float2 lam = g_lam[blk*HH + h];
    float2 lp = lam;
    #pragma unroll
    for (int i = 0; i < 8; i++) {
        float2 t;
        t.x = lp.x*lp.x - lp.y*lp.y;
        t.y = 2.f*lp.x*lp.y;
        lp = t;
    }
    float2 s = make_float2(0.f, 0.f);
    for (int c = 0; c < NCH; c++) {
        g_inc[(b*NCH + c)*HH + h] = s;
        float2 cr = g_carry[(b*NCH + c)*HH + h];
        s = cstep(lp, s, cr);
    }
}
__global__ void scanC_kernel(int blk) {
    int g  = blockIdx.x*256 + threadIdx.x;
    int h  = g & 255;
    int bc = g >> 8;
    int b  = bc >> 4;
    int c  = bc & 15;
    float2 lam = g_lam[blk*HH + h];
    float2 s = g_inc[bc*HH + h];
    uint32_t* bu = (uint32_t*)g_bu16 + ((size_t)(b*TT + c*CLEN)*256 + h);
    #pragma unroll 8
    for (int i = 0; i < CLEN; i++) {
        float2 u = bf2f(bu[(size_t)i*256]);
        s = cstep(lam, s, u);
        __nv_bfloat162 p = __floats2bfloat162_rn(s.x, s.y);
        bu[(size_t)i*256] = *(uint32_t*)&p;
    }
}

// ---------------- final: mean-pool + head ----------------
__global__ void final_kernel(const float* __restrict__ h,
                             const float* __restrict__ Wout,
                             const float* __restrict__ bout,
                             float* __restrict__ out) {
    __shared__ float pooled[DE];
    int b = blockIdx.x;
    int f = threadIdx.x;
    float s = 0.f;
    const float* p = h + (size_t)b*TT*DE + f;
    #pragma unroll 4
    for (int t = 0; t < TT; t++) s += p[(size_t)t*DE];
    pooled[f] = s * (1.f/TT);
    __syncthreads();
    if (f < OD) {
        float acc = bout[f];
        #pragma unroll 4
        for (int d = 0; d < DE; d++) acc = fmaf(pooled[d], Wout[d*OD + f], acc);
        out[b*OD + f] = acc;
    }
}

// ---------------- launch ----------------
#define SMEM_F32A (2*4*128*72*2)   // 147456
#define SMEM_BF16A (2*3*128*72*2)  // 110592

extern "C" void kernel_launch(void* const* d_in, const int* in_sizes, int n_in,
                              void* d_out, int out_size) {
    const float* x         = (const float*)d_in[0];
    const float* nu_log    = (const float*)d_in[1];
    const float* theta_log = (const float*)d_in[2];
    const float* B_re      = (const float*)d_in[3];
    const float* B_im      = (const float*)d_in[4];
    const float* C_re      = (const float*)d_in[5];
    const float* C_im      = (const float*)d_in[6];
    const float* D_lru     = (const float*)d_in[7];
    const float* W1        = (const float*)d_in[8];
    const float* b1        = (const float*)d_in[9];
    const float* W2        = (const float*)d_in[10];
    const float* b2        = (const float*)d_in[11];
    const float* bn_scale  = (const float*)d_in[12];
    const float* bn_bias   = (const float*)d_in[13];
    const float* W_enc     = (const float*)d_in[14];
    const float* b_enc     = (const float*)d_in[15];
    const float* W_out     = (const float*)d_in[16];
    const float* b_out     = (const float*)d_in[17];
    float* out = (float*)d_out;

    float *yenc, *h, *lru, *glu;
    __nv_bfloat16 *bu16, *wbh, *wbl, *wch, *wcl, *w1h, *w1l, *w2h, *w2l, *weh, *wel;
    cudaGetSymbolAddress((void**)&yenc, g_yenc);
    cudaGetSymbolAddress((void**)&h,    g_h);
    cudaGetSymbolAddress((void**)&bu16, g_bu16);
    cudaGetSymbolAddress((void**)&lru,  g_lru);
    cudaGetSymbolAddress((void**)&glu,  g_glu);
    cudaGetSymbolAddress((void**)&wbh,  g_WBh);
    cudaGetSymbolAddress((void**)&wbl,  g_WBl);
    cudaGetSymbolAddress((void**)&wch,  g_WCh);
    cudaGetSymbolAddress((void**)&wcl,  g_WCl);
    cudaGetSymbolAddress((void**)&w1h,  g_W1h);
    cudaGetSymbolAddress((void**)&w1l,  g_W1l);
    cudaGetSymbolAddress((void**)&w2h,  g_W2h);
    cudaGetSymbolAddress((void**)&w2l,  g_W2l);
    cudaGetSymbolAddress((void**)&weh,  g_WEh);
    cudaGetSymbolAddress((void**)&wel,  g_WEl);

    cudaFuncSetAttribute(gemm_mma<64, 128, 0, 0, 0, 0, 0>,  cudaFuncAttributeMaxDynamicSharedMemorySize, SMEM_F32A);
    cudaFuncSetAttribute(gemm_mma<128, 512, 1, 0, 0, 0, 1>, cudaFuncAttributeMaxDynamicSharedMemorySize, SMEM_F32A);
    cudaFuncSetAttribute(gemm_mma<512, 128, 0, 1, 0, 1, 0>, cudaFuncAttributeMaxDynamicSharedMemorySize, SMEM_BF16A);
    cudaFuncSetAttribute(gemm_mma<128, 256, 0, 0, 1, 0, 0>, cudaFuncAttributeMaxDynamicSharedMemorySize, SMEM_F32A);
    cudaFuncSetAttribute(gemm_mma<256, 128, 0, 2, 0, 0, 0>, cudaFuncAttributeMaxDynamicSharedMemorySize, SMEM_F32A);

    prep_lam_kernel<<<NBLKS, HH>>>(nu_log, theta_log);
    prep_WB_kernel<<<(NBLKS*512*DE + 255)/256, 256>>>(B_re, B_im);
    prep_WC_kernel<<<(NBLKS*DE*512 + 255)/256, 256>>>(C_re, C_im);
    prep_W1_kernel<<<(NBLKS*512*DE + 255)/256, 256>>>(W1);
    prep_W2_kernel<<<(NBLKS*DE*256 + 255)/256, 256>>>(W2);
    prep_WE_kernel<<<(DE*TSD + 255)/256, 256>>>(W_enc);

    // encoder: y_enc = x @ W_enc + b_enc
    gemm_mma<64, 128, 0, 0, 0, 0, 0><<<dim3(1, NR/128), 256, SMEM_F32A>>>(
        x, weh, wel, yenc, b_enc, nullptr, nullptr);

    const float* hp = yenc;
    for (int blk = 0; blk < NBLKS; blk++) {
        bn_stats1_kernel<<<512, 128>>>(hp);
        bn_stats2_kernel<<<1, 128>>>(bn_scale + blk*DE, bn_bias + blk*DE);

        // Bu = BN(h) @ WB   (bf16 output)
        gemm_mma<128, 512, 1, 0, 0, 0, 1><<<dim3(4, NR/128), 256, SMEM_F32A>>>(
            hp, wbh + (size_t)blk*512*128, wbl + (size_t)blk*512*128,
            (float*)bu16, nullptr, nullptr, nullptr);

        scanA_kernel<<<NR/256, 256>>>(blk);
        scanB_kernel<<<BB, HH>>>(blk);
        scanC_kernel<<<NR/256, 256>>>(blk);

        // lru = Re(state @ C) + BN(h) * D   (bf16 A)
        gemm_mma<512, 128, 0, 1, 0, 1, 0><<<dim3(1, NR/128), 256, SMEM_BF16A>>>(
            bu16, wch + (size_t)blk*128*512, wcl + (size_t)blk*128*512,
            lru, nullptr, hp, D_lru + blk*DE);

        // glu = GLU(lru @ W1 + b1)
        gemm_mma<128, 256, 0, 0, 1, 0, 0><<<dim3(4, NR/128), 256, SMEM_F32A>>>(
            lru, w1h + (size_t)blk*512*128, w1l + (size_t)blk*512*128,
            glu, b1 + (size_t)blk*LDF, nullptr, nullptr);

        // h = glu @ W2 + b2 + y_enc
        gemm_mma<256, 128, 0, 2, 0, 0, 0><<<dim3(1, NR/128), 256, SMEM_F32A>>>(
            glu, w2h + (size_t)blk*128*256, w2l + (size_t)blk*128*256,
            h, b2 + blk*DE, yenc, nullptr);

        hp = h;
    }

    final_kernel<<<BB, DE>>>(hp, W_out, b_out, out);
}